// round 12
// baseline (speedup 1.0000x reference)
#include <cuda_runtime.h>
#include <math.h>

#define B_  32
#define T_  2048
#define W_  10
#define BT_ (B_*T_)
#define NTH 256
#define PPB 128

typedef unsigned long long u64;

__device__ float g_ret[BT_];
__device__ float g_vol[BT_];
__device__ float g_Hl[BT_];

// ---------------- packed f32x2 helpers ----------------
__device__ __forceinline__ u64 pk2(float a, float b) {
    u64 r; asm("mov.b64 %0, {%1, %2};" : "=l"(r) : "f"(a), "f"(b)); return r;
}
__device__ __forceinline__ void fma2(u64 &d, u64 a, u64 b) {
    asm("fma.rn.f32x2 %0, %1, %2, %0;" : "+l"(d) : "l"(a), "l"(b));
}
__device__ __forceinline__ float2 up2(u64 a) {
    float2 f; asm("mov.b64 {%0, %1}, %2;" : "=f"(f.x), "=f"(f.y) : "l"(a)); return f;
}

// ---------------- K1: ret + vol ----------------
__global__ void k_scan(const float* __restrict__ F) {
    int b = blockIdx.x;
    int tid = threadIdx.x;
    __shared__ float sh[256];
    int base = tid * 8;
    const float* fb = F + (size_t)b * T_ * 5;
    float lp_prev = (base > 0) ? fb[(base - 1) * 5] : 0.f;
    float a[8];
    float run = 0.f;
#pragma unroll
    for (int k = 0; k < 8; k++) {
        int t = base + k;
        float lp = fb[t * 5];
        float r = (t == 0) ? 0.f : (lp - lp_prev);
        lp_prev = lp;
        g_ret[b * T_ + t] = r;
        run += fabsf(r);
        a[k] = run;
    }
    sh[tid] = run;
    __syncthreads();
    float acc = run;
    for (int off = 1; off < 256; off <<= 1) {
        float v = (tid >= off) ? sh[tid - off] : 0.f;
        __syncthreads();
        acc += v;
        sh[tid] = acc;
        __syncthreads();
    }
    float excl = acc - run;
#pragma unroll
    for (int k = 0; k < 8; k++) {
        int t = base + k;
        g_vol[b * T_ + t] = (excl + a[k]) / ((float)(t + 1) + 1e-8f);
    }
}

// ---------------- K2: windowed H MLP ----------------
__global__ void k_hmlp(const float* __restrict__ hw1, const float* __restrict__ hb1,
                       const float* __restrict__ hw2, const float* __restrict__ hb2,
                       const float* __restrict__ hw3, const float* __restrict__ hb3) {
    __shared__ float s1[10 * 32], sb1[32], s2[32 * 32], sb2[32], s3[32];
    __shared__ float sb3;
    int tid = threadIdx.x;
    for (int k = tid; k < 320; k += 256) s1[k] = hw1[k];
    for (int k = tid; k < 1024; k += 256) s2[k] = hw2[k];
    if (tid < 32) { sb1[tid] = hb1[tid]; sb2[tid] = hb2[tid]; s3[tid] = hw3[tid]; }
    if (tid == 0) sb3 = hb3[0];
    __syncthreads();
    const int TW = T_ - W_;
    int gid = blockIdx.x * 256 + tid;
    if (gid >= B_ * TW) return;
    int b = gid / TW, s = gid - b * TW;
    float rw[10];
#pragma unroll
    for (int j = 0; j < 10; j++) rw[j] = g_ret[b * T_ + s + j];
    float h1[32];
#pragma unroll
    for (int u = 0; u < 32; u++) {
        float acc = sb1[u];
#pragma unroll
        for (int j = 0; j < 10; j++) acc += rw[j] * s1[j * 32 + u];
        h1[u] = fmaxf(acc, 0.f);
    }
    float o = sb3;
#pragma unroll
    for (int v = 0; v < 32; v++) {
        float acc = sb2[v];
#pragma unroll
        for (int u = 0; u < 32; u++) acc += h1[u] * s2[u * 32 + v];
        o += fmaxf(acc, 0.f) * s3[v];
    }
    float Hval = 0.5f / (1.f + expf(-o));
    g_Hl[b * T_ + s + W_] = Hval;
    if (s == 0) {
        for (int t = 0; t < W_; t++) g_Hl[b * T_ + t] = Hval;
    }
}

// ---------------- SMEM layout (float offsets) ----------------
#define SM_SS    0        // 50*128 = 6400 : suffix sums S[j][e], j=0..9
#define SM_L2R   6400     // 25*128
#define SM_ZR    9600     // 25*128
#define SM_ZG    12800    // 25*128
#define SM_STG   16000    // 1600
#define SM_GTS   17600    // 4*128
#define SM_FEATP 18112    // 5*128
#define SM_PB1   18752
#define SM_PB2   18816
#define SM_PB3   18880
#define SM_PB4   18944
#define SM_B1    19008
#define SM_GAM   19072
#define SM_BET   19136
#define SM_RME   19200
#define SM_RVA   19264
#define SM_B2    19328
#define SM_W3    19360
#define SM_GW1   19392
#define SM_GB1   19456
#define SM_GW2   19488
#define SM_GB2   19616
#define SM_B3    19620
#define SM_FLOATS 19632
#define SMEM_BYTES (SM_FLOATS * 4)
// overlays: YS = 0 (69*128=8832, after l4); HB = 0 (64*128, after w1); PS = SM_ZG (2048)

__device__ __forceinline__ void stage(float* dst, const float* __restrict__ src,
                                      int nf, int tid) {
    const float4* s4 = (const float4*)src;
    float4* d4 = (float4*)dst;
    for (int k = tid; k < (nf >> 2); k += NTH) d4[k] = s4[k];
}

// GEMM pass: acc[c*4+pp] += z[row][8 pos of pg] * w[row][4 cols of cg]
__device__ __forceinline__ void gpass(const float* __restrict__ zb, const float* __restrict__ wb,
                                      int nrows, int pg8, int cg4, u64* acc) {
#pragma unroll 5
    for (int i = 0; i < nrows; i++) {
        float4 wv = *(const float4*)(wb + i * 64 + cg4);
        ulonglong2 z0 = *(const ulonglong2*)(zb + i * 128 + pg8);
        ulonglong2 z1 = *(const ulonglong2*)(zb + i * 128 + pg8 + 4);
        u64 w0 = pk2(wv.x, wv.x), w1d = pk2(wv.y, wv.y);
        u64 w2d = pk2(wv.z, wv.z), w3d = pk2(wv.w, wv.w);
        fma2(acc[0],  z0.x, w0);  fma2(acc[1],  z0.y, w0);  fma2(acc[2],  z1.x, w0);  fma2(acc[3],  z1.y, w0);
        fma2(acc[4],  z0.x, w1d); fma2(acc[5],  z0.y, w1d); fma2(acc[6],  z1.x, w1d); fma2(acc[7],  z1.y, w1d);
        fma2(acc[8],  z0.x, w2d); fma2(acc[9],  z0.y, w2d); fma2(acc[10], z1.x, w2d); fma2(acc[11], z1.y, w2d);
        fma2(acc[12], z0.x, w3d); fma2(acc[13], z0.y, w3d); fma2(acc[14], z1.x, w3d); fma2(acc[15], z1.y, w3d);
    }
}

// 32-col GEMM pass: acc[c*4+pp], c=0..1
__device__ __forceinline__ void gpass32(const float* __restrict__ zb, const float* __restrict__ wb,
                                        int nrows, int pg8, int cg2, u64* acc) {
#pragma unroll 8
    for (int i = 0; i < nrows; i++) {
        float2 wv = *(const float2*)(wb + i * 32 + cg2);
        ulonglong2 z0 = *(const ulonglong2*)(zb + i * 128 + pg8);
        ulonglong2 z1 = *(const ulonglong2*)(zb + i * 128 + pg8 + 4);
        u64 w0 = pk2(wv.x, wv.x), w1d = pk2(wv.y, wv.y);
        fma2(acc[0], z0.x, w0);  fma2(acc[1], z0.y, w0);  fma2(acc[2], z1.x, w0);  fma2(acc[3], z1.y, w0);
        fma2(acc[4], z0.x, w1d); fma2(acc[5], z0.y, w1d); fma2(acc[6], z1.x, w1d); fma2(acc[7], z1.y, w1d);
    }
}

// ---------------- K3: main fused kernel ----------------
__global__ void __launch_bounds__(NTH) k_main(
    const float* __restrict__ F,
    const float* __restrict__ gw1, const float* __restrict__ gb1,
    const float* __restrict__ gw2, const float* __restrict__ gb2,
    const float* __restrict__ p1,  const float* __restrict__ p1b,
    const float* __restrict__ p2,  const float* __restrict__ p2b,
    const float* __restrict__ p3,  const float* __restrict__ p3b,
    const float* __restrict__ p4,  const float* __restrict__ p4b,
    const float* __restrict__ w1,  const float* __restrict__ b1,
    const float* __restrict__ gamma, const float* __restrict__ beta,
    const float* __restrict__ rmean, const float* __restrict__ rvar,
    const float* __restrict__ w2,  const float* __restrict__ b2,
    const float* __restrict__ w3,  const float* __restrict__ b3,
    float* __restrict__ out)
{
    extern __shared__ float sm[];
    int tid = threadIdx.x;
    int pg = tid >> 4, cg = tid & 15;
    int pg8 = pg * 8, cg4 = cg * 4;
    int pos0 = blockIdx.x * PPB;
    float* ss  = sm + SM_SS;
    float* l2r = sm + SM_L2R;
    float* zr  = sm + SM_ZR;
    float* zg  = sm + SM_ZG;
    float* stg = sm + SM_STG;
    float* gts = sm + SM_GTS;

    // ---- phase 0: params (tid>=128) + signature suffix sums (tid<128) ----
    if (tid >= 128 && tid < 192) {
        int k = tid - 128;
        sm[SM_PB1 + k] = p1b[k]; sm[SM_PB2 + k] = p2b[k];
        sm[SM_PB3 + k] = p3b[k]; sm[SM_PB4 + k] = p4b[k];
        sm[SM_B1 + k] = b1[k];  sm[SM_GAM + k] = gamma[k];
        sm[SM_BET + k] = beta[k]; sm[SM_RME + k] = rmean[k];
        sm[SM_RVA + k] = rvar[k]; sm[SM_GW1 + k] = gw1[k];
    } else if (tid >= 192 && tid < 224) {
        int k = tid - 192;
        sm[SM_B2 + k] = b2[k]; sm[SM_W3 + k] = w3[k]; sm[SM_GB1 + k] = gb1[k];
    } else if (tid >= 224) {
        int k = tid - 224;
        for (int k2 = k; k2 < 128; k2 += 32) sm[SM_GW2 + k2] = gw2[k2];
        if (k < 4)  sm[SM_GB2 + k] = gb2[k];
        if (k == 4) sm[SM_B3] = b3[0];
    }

    int mypos = pos0 + (tid & 127);
    int myt = mypos & (T_ - 1);
    int myb = mypos >> 11;
    const float* fb = F + (size_t)myb * T_ * 5;

    if (tid < 128) {
        float S[5] = {0.f,0.f,0.f,0.f,0.f};
        float l2f[25];
#pragma unroll
        for (int i = 0; i < 25; i++) l2f[i] = 0.f;
        float rowH[5];
#pragma unroll
        for (int e = 0; e < 5; e++) {
            rowH[e] = fb[myt * 5 + e];
            sm[SM_FEATP + e * 128 + tid] = rowH[e];
        }
#pragma unroll
        for (int r = W_ - 1; r >= 0; r--) {
            int i0 = myt - W_ + r;
            bool valid = (i0 >= 0);
            float Dw[5], rowL[5];
#pragma unroll
            for (int e = 0; e < 5; e++) {
                rowL[e] = valid ? fb[i0 * 5 + e] : 0.f;
                Dw[e] = valid ? (rowH[e] - rowL[e]) : 0.f;
            }
#pragma unroll
            for (int e = 0; e < 5; e++) {
                S[e] += Dw[e];
                ss[(r * 5 + e) * 128 + tid] = S[e];
            }
#pragma unroll
            for (int e = 0; e < 5; e++)
#pragma unroll
                for (int f = 0; f < 5; f++) l2f[e * 5 + f] += Dw[e] * S[f];
#pragma unroll
            for (int e = 0; e < 5; e++) rowH[e] = rowL[e];
        }
#pragma unroll
        for (int i = 0; i < 25; i++) l2r[i * 128 + tid] = l2f[i];
    }
    __syncthreads();

    // ---- phase 1: gate (tid<128) + stage lvl1 weights ----
    stage(stg +   0, p1, 320, tid);
    stage(stg + 320, p2, 320, tid);
    stage(stg + 640, p3, 320, tid);
    stage(stg + 960, p4, 320, tid);
    if (tid < 128) {
        float Hv = g_Hl[mypos], vv = g_vol[mypos];
        float L0 = sm[SM_GB2+0], L1 = sm[SM_GB2+1], L2 = sm[SM_GB2+2], L3 = sm[SM_GB2+3];
#pragma unroll
        for (int u = 0; u < 32; u++) {
            float gh = fmaxf(Hv * sm[SM_GW1 + u] + vv * sm[SM_GW1 + 32 + u] + sm[SM_GB1 + u], 0.f);
            L0 += gh * sm[SM_GW2 + u*4 + 0];
            L1 += gh * sm[SM_GW2 + u*4 + 1];
            L2 += gh * sm[SM_GW2 + u*4 + 2];
            L3 += gh * sm[SM_GW2 + u*4 + 3];
        }
        float mx = fmaxf(fmaxf(L0,L1), fmaxf(L2,L3));
        float e0 = expf(L0-mx), e1 = expf(L1-mx), e2 = expf(L2-mx), e3 = expf(L3-mx);
        float inv = 1.f / (e0+e1+e2+e3);
        gts[       tid] = e0 * inv;
        gts[128 + tid] = (myt >= 1) ? e1 * inv : 0.f;
        gts[256 + tid] = (myt >= 2) ? e2 * inv : 0.f;
        gts[384 + tid] = (myt >= 3) ? e3 * inv : 0.f;
    }
    __syncthreads();

    // ---- acc init from gated biases + lvl1 zg gen ----
    u64 acc[16];
#pragma unroll
    for (int pp = 0; pp < 4; pp++) {
        int pl0 = pg8 + 2*pp;
        float ga0 = gts[pl0],     ga1 = gts[128+pl0], ga2 = gts[256+pl0], ga3 = gts[384+pl0];
        float gb0 = gts[pl0+1],   gb1v = gts[128+pl0+1], gb2v = gts[256+pl0+1], gb3v = gts[384+pl0+1];
#pragma unroll
        for (int c = 0; c < 4; c++) {
            int col = cg4 + c;
            float ve = ga0*sm[SM_PB1+col] + ga1*sm[SM_PB2+col] + ga2*sm[SM_PB3+col] + ga3*sm[SM_PB4+col];
            float vo = gb0*sm[SM_PB1+col] + gb1v*sm[SM_PB2+col] + gb2v*sm[SM_PB3+col] + gb3v*sm[SM_PB4+col];
            acc[c*4+pp] = pk2(ve, vo);
        }
    }
    {
        int pos = tid & 127, h = tid >> 7;
        for (int k = 0; k < 10; k++) {
            int i = h + 2*k;
            if (i < 20) {
                int lvl = i / 5, e = i - 5*lvl;
                zg[i * 128 + pos] = ss[e * 128 + pos] * gts[lvl * 128 + pos];
            }
        }
    }
    __syncthreads();
    gpass(zg, stg, 20, pg8, cg4, acc);
    __syncthreads();

    // ---- l2 chunks: p2(g1), p3(g2), p4(g3) ----
    {
        int pos = tid & 127, h = tid >> 7;
        const float* pmat[3] = { p2, p3, p4 };
        for (int m = 0; m < 3; m++) {
            stage(stg, pmat[m] + 5 * 64, 1600, tid);
            float gv = gts[(m+1) * 128 + pos];
            for (int k = 0; k < 13; k++) {
                int i = h + 2*k;
                if (i < 25) zg[i * 128 + pos] = l2r[i * 128 + pos] * gv;
            }
            __syncthreads();
            gpass(zg, stg, 25, pg8, cg4, acc);
            __syncthreads();
        }
    }

    // ---- l3 chunks: per dd, gen zr once, gate for p3(g2) then p4(g3) ----
    {
        int pos = tid & 127, h = tid >> 7;
        for (int dd = 0; dd < 5; dd++) {
            // cooperative raw l3 chunk gen from suffix sums
            float Tot = ss[dd * 128 + pos];
            float ssj[5] = {0.f,0.f,0.f,0.f,0.f};
            if (h == 0) {
                float a0[5], a1[5], a2[5];
#pragma unroll
                for (int f = 0; f < 5; f++) { a0[f]=0.f; a1[f]=0.f; a2[f]=0.f; }
#pragma unroll
                for (int j = 9; j >= 0; j--) {
                    float ssc[5];
#pragma unroll
                    for (int e = 0; e < 5; e++) ssc[e] = ss[(j*5+e)*128 + pos];
                    float pj = Tot - ssc[dd];
                    float t0 = pj * (ssc[0]-ssj[0]);
                    float t1 = pj * (ssc[1]-ssj[1]);
                    float t2 = pj * (ssc[2]-ssj[2]);
#pragma unroll
                    for (int f = 0; f < 5; f++) {
                        a0[f] += t0 * ssc[f];
                        a1[f] += t1 * ssc[f];
                        a2[f] += t2 * ssc[f];
                    }
#pragma unroll
                    for (int e = 0; e < 5; e++) ssj[e] = ssc[e];
                }
#pragma unroll
                for (int f = 0; f < 5; f++) {
                    zr[(0*5+f)*128+pos] = a0[f];
                    zr[(1*5+f)*128+pos] = a1[f];
                    zr[(2*5+f)*128+pos] = a2[f];
                }
            } else {
                float a3[5], a4[5];
#pragma unroll
                for (int f = 0; f < 5; f++) { a3[f]=0.f; a4[f]=0.f; }
#pragma unroll
                for (int j = 9; j >= 0; j--) {
                    float ssc[5];
#pragma unroll
                    for (int e = 0; e < 5; e++) ssc[e] = ss[(j*5+e)*128 + pos];
                    float pj = Tot - ssc[dd];
                    float t3 = pj * (ssc[3]-ssj[3]);
                    float t4 = pj * (ssc[4]-ssj[4]);
#pragma unroll
                    for (int f = 0; f < 5; f++) {
                        a3[f] += t3 * ssc[f];
                        a4[f] += t4 * ssc[f];
                    }
#pragma unroll
                    for (int e = 0; e < 5; e++) ssj[e] = ssc[e];
                }
#pragma unroll
                for (int f = 0; f < 5; f++) {
                    zr[(3*5+f)*128+pos] = a3[f];
                    zr[(4*5+f)*128+pos] = a4[f];
                }
            }
            __syncthreads();
            // two gated passes
            for (int m = 0; m < 2; m++) {
                const float* wsrc = (m == 0) ? (p3 + (30 + dd*25) * 64) : (p4 + (30 + dd*25) * 64);
                stage(stg, wsrc, 1600, tid);
                float gv = gts[(m+2) * 128 + pos];
                for (int k = 0; k < 13; k++) {
                    int i = h + 2*k;
                    if (i < 25) zg[i * 128 + pos] = zr[i * 128 + pos] * gv;
                }
                __syncthreads();
                gpass(zg, stg, 25, pg8, cg4, acc);
                __syncthreads();
            }
        }
    }

    // ---- l4 chunks: per a, zg = l2[a]*l2[b]*g3 ----
    {
        int pos = tid & 127, h = tid >> 7;
        float g3v = gts[384 + pos];
        for (int a = 0; a < 25; a++) {
            stage(stg, p4 + (155 + a*25) * 64, 1600, tid);
            float la = l2r[a * 128 + pos] * g3v;
            for (int k = 0; k < 13; k++) {
                int i = h + 2*k;
                if (i < 25) zg[i * 128 + pos] = la * l2r[i * 128 + pos];
            }
            __syncthreads();
            gpass(zg, stg, 25, pg8, cg4, acc);
            __syncthreads();
        }
    }

    // ---- write y -> ys [col][pos] (overlay on ss/l2r, both dead) + feat rows ----
    float* ys = sm + SM_SS;   // 69*128
#pragma unroll
    for (int c = 0; c < 4; c++)
#pragma unroll
        for (int pp = 0; pp < 4; pp++)
            *(u64*)(ys + (cg4 + c) * 128 + pg8 + 2*pp) = acc[c*4+pp];
    {
        int pos = tid & 127, h = tid >> 7;
        for (int k = 0; k < 3; k++) {
            int e = h + 2*k;
            if (e < 5) ys[(64 + e) * 128 + pos] = sm[SM_FEATP + e * 128 + pos];
        }
    }
    __syncthreads();

    // ---- h1 = relu([y, feat] @ w1 + b1), 3 chunks ----
#pragma unroll
    for (int pp = 0; pp < 4; pp++)
#pragma unroll
        for (int c = 0; c < 4; c++) {
            float bv = sm[SM_B1 + cg4 + c];
            acc[c*4+pp] = pk2(bv, bv);
        }
    stage(stg, w1, 1600, tid);
    __syncthreads();
    gpass(ys, stg, 25, pg8, cg4, acc);
    __syncthreads();
    stage(stg, w1 + 25*64, 1600, tid);
    __syncthreads();
    gpass(ys + 25*128, stg, 25, pg8, cg4, acc);
    __syncthreads();
    stage(stg, w1 + 50*64, 19*64, tid);
    __syncthreads();
    gpass(ys + 50*128, stg, 19, pg8, cg4, acc);
    __syncthreads();

    // ---- BN(relu(h1)) -> hb [col][pos] (overlay on ys, dead) ----
    float* hb = sm + SM_SS;
#pragma unroll
    for (int c = 0; c < 4; c++) {
        int col = cg4 + c;
        float gam = sm[SM_GAM+col], bet = sm[SM_BET+col];
        float rme = sm[SM_RME+col], rva = rsqrtf(sm[SM_RVA+col] + 1e-5f);
#pragma unroll
        for (int pp = 0; pp < 4; pp++) {
            float2 h = up2(acc[c*4+pp]);
            float bx = gam * (fmaxf(h.x, 0.f) - rme) * rva + bet;
            float by = gam * (fmaxf(h.y, 0.f) - rme) * rva + bet;
            *(u64*)(hb + col * 128 + pg8 + 2*pp) = pk2(bx, by);
        }
    }
    __syncthreads();

    // ---- h2 = relu(hb @ w2 + b2), 2 chunks of 32 rows ----
    int cg2 = cg * 2;
    u64 acc8[8];
#pragma unroll
    for (int pp = 0; pp < 4; pp++)
#pragma unroll
        for (int c = 0; c < 2; c++) {
            float bv = sm[SM_B2 + cg2 + c];
            acc8[c*4+pp] = pk2(bv, bv);
        }
    stage(stg, w2, 1024, tid);
    __syncthreads();
    gpass32(hb, stg, 32, pg8, cg2, acc8);
    __syncthreads();
    stage(stg, w2 + 1024, 1024, tid);
    __syncthreads();
    gpass32(hb + 32*128, stg, 32, pg8, cg2, acc8);
    __syncthreads();

    // ---- final: partials + reduce + tanh ----
    float* ps = sm + SM_ZG;   // 128*16
    {
        float w3a = sm[SM_W3 + cg2], w3b = sm[SM_W3 + cg2 + 1];
#pragma unroll
        for (int pp = 0; pp < 4; pp++) {
            float2 f0 = up2(acc8[0*4+pp]);
            float2 f1 = up2(acc8[1*4+pp]);
            ps[(pg8 + 2*pp)     * 16 + cg] = fmaxf(f0.x, 0.f) * w3a + fmaxf(f1.x, 0.f) * w3b;
            ps[(pg8 + 2*pp + 1) * 16 + cg] = fmaxf(f0.y, 0.f) * w3a + fmaxf(f1.y, 0.f) * w3b;
        }
    }
    __syncthreads();
    if (tid < 128) {
        float o = sm[SM_B3];
#pragma unroll
        for (int c = 0; c < 16; c += 4) {
            float4 v = *(const float4*)(ps + tid * 16 + c);
            o += v.x + v.y + v.z + v.w;
        }
        out[pos0 + tid] = 1.5f * tanhf(o);
    }
}

extern "C" void kernel_launch(void* const* d_in, const int* in_sizes, int n_in,
                              void* d_out, int out_size) {
    const float* F    = (const float*)d_in[0];
    const float* hw1  = (const float*)d_in[1];
    const float* hb1  = (const float*)d_in[2];
    const float* hw2  = (const float*)d_in[3];
    const float* hb2  = (const float*)d_in[4];
    const float* hw3  = (const float*)d_in[5];
    const float* hb3  = (const float*)d_in[6];
    const float* gw1  = (const float*)d_in[7];
    const float* gb1  = (const float*)d_in[8];
    const float* gw2  = (const float*)d_in[9];
    const float* gb2  = (const float*)d_in[10];
    const float* p1   = (const float*)d_in[11];
    const float* p1b  = (const float*)d_in[12];
    const float* p2   = (const float*)d_in[13];
    const float* p2b  = (const float*)d_in[14];
    const float* p3   = (const float*)d_in[15];
    const float* p3b  = (const float*)d_in[16];
    const float* p4   = (const float*)d_in[17];
    const float* p4b  = (const float*)d_in[18];
    const float* w1   = (const float*)d_in[19];
    const float* b1   = (const float*)d_in[20];
    const float* gm   = (const float*)d_in[21];
    const float* bt   = (const float*)d_in[22];
    const float* rmean= (const float*)d_in[23];
    const float* rvar = (const float*)d_in[24];
    const float* w2   = (const float*)d_in[25];
    const float* b2   = (const float*)d_in[26];
    const float* w3   = (const float*)d_in[27];
    const float* b3   = (const float*)d_in[28];

    cudaFuncSetAttribute(k_main, cudaFuncAttributeMaxDynamicSharedMemorySize, SMEM_BYTES);

    k_scan<<<B_, 256>>>(F);
    k_hmlp<<<(B_ * (T_ - W_) + 255) / 256, 256>>>(hw1, hb1, hw2, hb2, hw3, hb3);
    k_main<<<BT_ / PPB, NTH, SMEM_BYTES>>>(F, gw1, gb1, gw2, gb2,
                                           p1, p1b, p2, p2b, p3, p3b, p4, p4b,
                                           w1, b1, gm, bt, rmean, rvar,
                                           w2, b2, w3, b3, (float*)d_out);
}

// round 13
// speedup vs baseline: 1.0016x; 1.0016x over previous
#include <cuda_runtime.h>
#include <math.h>

#define B_  32
#define T_  2048
#define W_  10
#define BT_ (B_*T_)
#define NTH 256
#define PPB 128

typedef unsigned long long u64;

__device__ float g_ret[BT_];
__device__ float g_vol[BT_];
__device__ float g_Hl[BT_];

// ---------------- packed f32x2 helpers ----------------
__device__ __forceinline__ u64 pk2(float a, float b) {
    u64 r; asm("mov.b64 %0, {%1, %2};" : "=l"(r) : "f"(a), "f"(b)); return r;
}
__device__ __forceinline__ void fma2(u64 &d, u64 a, u64 b) {
    asm("fma.rn.f32x2 %0, %1, %2, %0;" : "+l"(d) : "l"(a), "l"(b));
}
__device__ __forceinline__ float2 up2(u64 a) {
    float2 f; asm("mov.b64 {%0, %1}, %2;" : "=f"(f.x), "=f"(f.y) : "l"(a)); return f;
}

// ---------------- K1: ret + vol ----------------
__global__ void k_scan(const float* __restrict__ F) {
    int b = blockIdx.x;
    int tid = threadIdx.x;
    __shared__ float sh[256];
    int base = tid * 8;
    const float* fb = F + (size_t)b * T_ * 5;
    float lp_prev = (base > 0) ? fb[(base - 1) * 5] : 0.f;
    float a[8];
    float run = 0.f;
#pragma unroll
    for (int k = 0; k < 8; k++) {
        int t = base + k;
        float lp = fb[t * 5];
        float r = (t == 0) ? 0.f : (lp - lp_prev);
        lp_prev = lp;
        g_ret[b * T_ + t] = r;
        run += fabsf(r);
        a[k] = run;
    }
    sh[tid] = run;
    __syncthreads();
    float acc = run;
    for (int off = 1; off < 256; off <<= 1) {
        float v = (tid >= off) ? sh[tid - off] : 0.f;
        __syncthreads();
        acc += v;
        sh[tid] = acc;
        __syncthreads();
    }
    float excl = acc - run;
#pragma unroll
    for (int k = 0; k < 8; k++) {
        int t = base + k;
        g_vol[b * T_ + t] = (excl + a[k]) / ((float)(t + 1) + 1e-8f);
    }
}

// ---------------- K2: windowed H MLP ----------------
__global__ void k_hmlp(const float* __restrict__ hw1, const float* __restrict__ hb1,
                       const float* __restrict__ hw2, const float* __restrict__ hb2,
                       const float* __restrict__ hw3, const float* __restrict__ hb3) {
    __shared__ float s1[10 * 32], sb1[32], s2[32 * 32], sb2[32], s3[32];
    __shared__ float sb3;
    int tid = threadIdx.x;
    for (int k = tid; k < 320; k += 256) s1[k] = hw1[k];
    for (int k = tid; k < 1024; k += 256) s2[k] = hw2[k];
    if (tid < 32) { sb1[tid] = hb1[tid]; sb2[tid] = hb2[tid]; s3[tid] = hw3[tid]; }
    if (tid == 0) sb3 = hb3[0];
    __syncthreads();
    const int TW = T_ - W_;
    int gid = blockIdx.x * 256 + tid;
    if (gid >= B_ * TW) return;
    int b = gid / TW, s = gid - b * TW;
    float rw[10];
#pragma unroll
    for (int j = 0; j < 10; j++) rw[j] = g_ret[b * T_ + s + j];
    float h1[32];
#pragma unroll
    for (int u = 0; u < 32; u++) {
        float acc = sb1[u];
#pragma unroll
        for (int j = 0; j < 10; j++) acc += rw[j] * s1[j * 32 + u];
        h1[u] = fmaxf(acc, 0.f);
    }
    float o = sb3;
#pragma unroll
    for (int v = 0; v < 32; v++) {
        float acc = sb2[v];
#pragma unroll
        for (int u = 0; u < 32; u++) acc += h1[u] * s2[u * 32 + v];
        o += fmaxf(acc, 0.f) * s3[v];
    }
    float Hval = 0.5f / (1.f + expf(-o));
    g_Hl[b * T_ + s + W_] = Hval;
    if (s == 0) {
        for (int t = 0; t < W_; t++) g_Hl[b * T_ + t] = Hval;
    }
}

// ---------------- SMEM layout (float offsets) ----------------
#define SM_SS    0        // 50*128 = 6400 : suffix sums S[j][e], j=0..9
#define SM_L2R   6400     // 25*128
#define SM_ZR    9600     // 25*128
#define SM_ZG    12800    // 25*128
#define SM_STG   16000    // 1600
#define SM_GTS   17600    // 4*128
#define SM_FEATP 18112    // 5*128
#define SM_PB1   18752
#define SM_PB2   18816
#define SM_PB3   18880
#define SM_PB4   18944
#define SM_B1    19008
#define SM_GAM   19072
#define SM_BET   19136
#define SM_RME   19200
#define SM_RVA   19264
#define SM_B2    19328
#define SM_W3    19360
#define SM_GW1   19392
#define SM_GB1   19456
#define SM_GW2   19488
#define SM_GB2   19616
#define SM_B3    19620
#define SM_FLOATS 19632
#define SMEM_BYTES (SM_FLOATS * 4)
// overlays: YS = 0 (69*128=8832, after l4); HB = 0 (64*128, after w1); PS = SM_ZG (2048)

__device__ __forceinline__ void stage(float* dst, const float* __restrict__ src,
                                      int nf, int tid) {
    const float4* s4 = (const float4*)src;
    float4* d4 = (float4*)dst;
    for (int k = tid; k < (nf >> 2); k += NTH) d4[k] = s4[k];
}

// GEMM pass: acc[c*4+pp] += z[row][8 pos of pg] * w[row][4 cols of cg]
__device__ __forceinline__ void gpass(const float* __restrict__ zb, const float* __restrict__ wb,
                                      int nrows, int pg8, int cg4, u64* acc) {
#pragma unroll 5
    for (int i = 0; i < nrows; i++) {
        float4 wv = *(const float4*)(wb + i * 64 + cg4);
        ulonglong2 z0 = *(const ulonglong2*)(zb + i * 128 + pg8);
        ulonglong2 z1 = *(const ulonglong2*)(zb + i * 128 + pg8 + 4);
        u64 w0 = pk2(wv.x, wv.x), w1d = pk2(wv.y, wv.y);
        u64 w2d = pk2(wv.z, wv.z), w3d = pk2(wv.w, wv.w);
        fma2(acc[0],  z0.x, w0);  fma2(acc[1],  z0.y, w0);  fma2(acc[2],  z1.x, w0);  fma2(acc[3],  z1.y, w0);
        fma2(acc[4],  z0.x, w1d); fma2(acc[5],  z0.y, w1d); fma2(acc[6],  z1.x, w1d); fma2(acc[7],  z1.y, w1d);
        fma2(acc[8],  z0.x, w2d); fma2(acc[9],  z0.y, w2d); fma2(acc[10], z1.x, w2d); fma2(acc[11], z1.y, w2d);
        fma2(acc[12], z0.x, w3d); fma2(acc[13], z0.y, w3d); fma2(acc[14], z1.x, w3d); fma2(acc[15], z1.y, w3d);
    }
}

// 32-col GEMM pass: acc[c*4+pp], c=0..1
__device__ __forceinline__ void gpass32(const float* __restrict__ zb, const float* __restrict__ wb,
                                        int nrows, int pg8, int cg2, u64* acc) {
#pragma unroll 8
    for (int i = 0; i < nrows; i++) {
        float2 wv = *(const float2*)(wb + i * 32 + cg2);
        ulonglong2 z0 = *(const ulonglong2*)(zb + i * 128 + pg8);
        ulonglong2 z1 = *(const ulonglong2*)(zb + i * 128 + pg8 + 4);
        u64 w0 = pk2(wv.x, wv.x), w1d = pk2(wv.y, wv.y);
        fma2(acc[0], z0.x, w0);  fma2(acc[1], z0.y, w0);  fma2(acc[2], z1.x, w0);  fma2(acc[3], z1.y, w0);
        fma2(acc[4], z0.x, w1d); fma2(acc[5], z0.y, w1d); fma2(acc[6], z1.x, w1d); fma2(acc[7], z1.y, w1d);
    }
}

// ---------------- K3: main fused kernel ----------------
__global__ void __launch_bounds__(NTH) k_main(
    const float* __restrict__ F,
    const float* __restrict__ gw1, const float* __restrict__ gb1,
    const float* __restrict__ gw2, const float* __restrict__ gb2,
    const float* __restrict__ p1,  const float* __restrict__ p1b,
    const float* __restrict__ p2,  const float* __restrict__ p2b,
    const float* __restrict__ p3,  const float* __restrict__ p3b,
    const float* __restrict__ p4,  const float* __restrict__ p4b,
    const float* __restrict__ w1,  const float* __restrict__ b1,
    const float* __restrict__ gamma, const float* __restrict__ beta,
    const float* __restrict__ rmean, const float* __restrict__ rvar,
    const float* __restrict__ w2,  const float* __restrict__ b2,
    const float* __restrict__ w3,  const float* __restrict__ b3,
    float* __restrict__ out)
{
    extern __shared__ float sm[];
    int tid = threadIdx.x;
    int pg = tid >> 4, cg = tid & 15;
    int pg8 = pg * 8, cg4 = cg * 4;
    int pos0 = blockIdx.x * PPB;
    float* ss  = sm + SM_SS;
    float* l2r = sm + SM_L2R;
    float* zr  = sm + SM_ZR;
    float* zg  = sm + SM_ZG;
    float* stg = sm + SM_STG;
    float* gts = sm + SM_GTS;

    // ---- phase 0: params (tid>=128) + signature suffix sums (tid<128) ----
    if (tid >= 128 && tid < 192) {
        int k = tid - 128;
        sm[SM_PB1 + k] = p1b[k]; sm[SM_PB2 + k] = p2b[k];
        sm[SM_PB3 + k] = p3b[k]; sm[SM_PB4 + k] = p4b[k];
        sm[SM_B1 + k] = b1[k];  sm[SM_GAM + k] = gamma[k];
        sm[SM_BET + k] = beta[k]; sm[SM_RME + k] = rmean[k];
        sm[SM_RVA + k] = rvar[k]; sm[SM_GW1 + k] = gw1[k];
    } else if (tid >= 192 && tid < 224) {
        int k = tid - 192;
        sm[SM_B2 + k] = b2[k]; sm[SM_W3 + k] = w3[k]; sm[SM_GB1 + k] = gb1[k];
    } else if (tid >= 224) {
        int k = tid - 224;
        for (int k2 = k; k2 < 128; k2 += 32) sm[SM_GW2 + k2] = gw2[k2];
        if (k < 4)  sm[SM_GB2 + k] = gb2[k];
        if (k == 4) sm[SM_B3] = b3[0];
    }

    int mypos = pos0 + (tid & 127);
    int myt = mypos & (T_ - 1);
    int myb = mypos >> 11;
    const float* fb = F + (size_t)myb * T_ * 5;

    if (tid < 128) {
        float S[5] = {0.f,0.f,0.f,0.f,0.f};
        float l2f[25];
#pragma unroll
        for (int i = 0; i < 25; i++) l2f[i] = 0.f;
        float rowH[5];
#pragma unroll
        for (int e = 0; e < 5; e++) {
            rowH[e] = fb[myt * 5 + e];
            sm[SM_FEATP + e * 128 + tid] = rowH[e];
        }
#pragma unroll
        for (int r = W_ - 1; r >= 0; r--) {
            int i0 = myt - W_ + r;
            bool valid = (i0 >= 0);
            float Dw[5], rowL[5];
#pragma unroll
            for (int e = 0; e < 5; e++) {
                rowL[e] = valid ? fb[i0 * 5 + e] : 0.f;
                Dw[e] = valid ? (rowH[e] - rowL[e]) : 0.f;
            }
#pragma unroll
            for (int e = 0; e < 5; e++) {
                S[e] += Dw[e];
                ss[(r * 5 + e) * 128 + tid] = S[e];
            }
#pragma unroll
            for (int e = 0; e < 5; e++)
#pragma unroll
                for (int f = 0; f < 5; f++) l2f[e * 5 + f] += Dw[e] * S[f];
#pragma unroll
            for (int e = 0; e < 5; e++) rowH[e] = rowL[e];
        }
#pragma unroll
        for (int i = 0; i < 25; i++) l2r[i * 128 + tid] = l2f[i];
    }
    __syncthreads();

    // ---- phase 1: gate (tid<128) + stage lvl1 weights ----
    stage(stg +   0, p1, 320, tid);
    stage(stg + 320, p2, 320, tid);
    stage(stg + 640, p3, 320, tid);
    stage(stg + 960, p4, 320, tid);
    if (tid < 128) {
        float Hv = g_Hl[mypos], vv = g_vol[mypos];
        float L0 = sm[SM_GB2+0], L1 = sm[SM_GB2+1], L2 = sm[SM_GB2+2], L3 = sm[SM_GB2+3];
#pragma unroll
        for (int u = 0; u < 32; u++) {
            float gh = fmaxf(Hv * sm[SM_GW1 + u] + vv * sm[SM_GW1 + 32 + u] + sm[SM_GB1 + u], 0.f);
            L0 += gh * sm[SM_GW2 + u*4 + 0];
            L1 += gh * sm[SM_GW2 + u*4 + 1];
            L2 += gh * sm[SM_GW2 + u*4 + 2];
            L3 += gh * sm[SM_GW2 + u*4 + 3];
        }
        float mx = fmaxf(fmaxf(L0,L1), fmaxf(L2,L3));
        float e0 = expf(L0-mx), e1 = expf(L1-mx), e2 = expf(L2-mx), e3 = expf(L3-mx);
        float inv = 1.f / (e0+e1+e2+e3);
        gts[       tid] = e0 * inv;
        gts[128 + tid] = (myt >= 1) ? e1 * inv : 0.f;
        gts[256 + tid] = (myt >= 2) ? e2 * inv : 0.f;
        gts[384 + tid] = (myt >= 3) ? e3 * inv : 0.f;
    }
    __syncthreads();

    // ---- acc init from gated biases + lvl1 zg gen ----
    u64 acc[16];
#pragma unroll
    for (int pp = 0; pp < 4; pp++) {
        int pl0 = pg8 + 2*pp;
        float ga0 = gts[pl0],     ga1 = gts[128+pl0], ga2 = gts[256+pl0], ga3 = gts[384+pl0];
        float gb0 = gts[pl0+1],   gb1v = gts[128+pl0+1], gb2v = gts[256+pl0+1], gb3v = gts[384+pl0+1];
#pragma unroll
        for (int c = 0; c < 4; c++) {
            int col = cg4 + c;
            float ve = ga0*sm[SM_PB1+col] + ga1*sm[SM_PB2+col] + ga2*sm[SM_PB3+col] + ga3*sm[SM_PB4+col];
            float vo = gb0*sm[SM_PB1+col] + gb1v*sm[SM_PB2+col] + gb2v*sm[SM_PB3+col] + gb3v*sm[SM_PB4+col];
            acc[c*4+pp] = pk2(ve, vo);
        }
    }
    {
        int pos = tid & 127, h = tid >> 7;
        for (int k = 0; k < 10; k++) {
            int i = h + 2*k;
            if (i < 20) {
                int lvl = i / 5, e = i - 5*lvl;
                zg[i * 128 + pos] = ss[e * 128 + pos] * gts[lvl * 128 + pos];
            }
        }
    }
    __syncthreads();
    gpass(zg, stg, 20, pg8, cg4, acc);
    __syncthreads();

    // ---- l2 chunks: p2(g1), p3(g2), p4(g3) ----
    {
        int pos = tid & 127, h = tid >> 7;
        const float* pmat[3] = { p2, p3, p4 };
        for (int m = 0; m < 3; m++) {
            stage(stg, pmat[m] + 5 * 64, 1600, tid);
            float gv = gts[(m+1) * 128 + pos];
            for (int k = 0; k < 13; k++) {
                int i = h + 2*k;
                if (i < 25) zg[i * 128 + pos] = l2r[i * 128 + pos] * gv;
            }
            __syncthreads();
            gpass(zg, stg, 25, pg8, cg4, acc);
            __syncthreads();
        }
    }

    // ---- l3 chunks: per dd, gen zr once, gate for p3(g2) then p4(g3) ----
    {
        int pos = tid & 127, h = tid >> 7;
        for (int dd = 0; dd < 5; dd++) {
            // cooperative raw l3 chunk gen from suffix sums
            float Tot = ss[dd * 128 + pos];
            float ssj[5] = {0.f,0.f,0.f,0.f,0.f};
            if (h == 0) {
                float a0[5], a1[5], a2[5];
#pragma unroll
                for (int f = 0; f < 5; f++) { a0[f]=0.f; a1[f]=0.f; a2[f]=0.f; }
#pragma unroll
                for (int j = 9; j >= 0; j--) {
                    float ssc[5];
#pragma unroll
                    for (int e = 0; e < 5; e++) ssc[e] = ss[(j*5+e)*128 + pos];
                    float pj = Tot - ssc[dd];
                    float t0 = pj * (ssc[0]-ssj[0]);
                    float t1 = pj * (ssc[1]-ssj[1]);
                    float t2 = pj * (ssc[2]-ssj[2]);
#pragma unroll
                    for (int f = 0; f < 5; f++) {
                        a0[f] += t0 * ssc[f];
                        a1[f] += t1 * ssc[f];
                        a2[f] += t2 * ssc[f];
                    }
#pragma unroll
                    for (int e = 0; e < 5; e++) ssj[e] = ssc[e];
                }
#pragma unroll
                for (int f = 0; f < 5; f++) {
                    zr[(0*5+f)*128+pos] = a0[f];
                    zr[(1*5+f)*128+pos] = a1[f];
                    zr[(2*5+f)*128+pos] = a2[f];
                }
            } else {
                float a3[5], a4[5];
#pragma unroll
                for (int f = 0; f < 5; f++) { a3[f]=0.f; a4[f]=0.f; }
#pragma unroll
                for (int j = 9; j >= 0; j--) {
                    float ssc[5];
#pragma unroll
                    for (int e = 0; e < 5; e++) ssc[e] = ss[(j*5+e)*128 + pos];
                    float pj = Tot - ssc[dd];
                    float t3 = pj * (ssc[3]-ssj[3]);
                    float t4 = pj * (ssc[4]-ssj[4]);
#pragma unroll
                    for (int f = 0; f < 5; f++) {
                        a3[f] += t3 * ssc[f];
                        a4[f] += t4 * ssc[f];
                    }
#pragma unroll
                    for (int e = 0; e < 5; e++) ssj[e] = ssc[e];
                }
#pragma unroll
                for (int f = 0; f < 5; f++) {
                    zr[(3*5+f)*128+pos] = a3[f];
                    zr[(4*5+f)*128+pos] = a4[f];
                }
            }
            __syncthreads();
            // two gated passes
            for (int m = 0; m < 2; m++) {
                const float* wsrc = (m == 0) ? (p3 + (30 + dd*25) * 64) : (p4 + (30 + dd*25) * 64);
                stage(stg, wsrc, 1600, tid);
                float gv = gts[(m+2) * 128 + pos];
                for (int k = 0; k < 13; k++) {
                    int i = h + 2*k;
                    if (i < 25) zg[i * 128 + pos] = zr[i * 128 + pos] * gv;
                }
                __syncthreads();
                gpass(zg, stg, 25, pg8, cg4, acc);
                __syncthreads();
            }
        }
    }

    // ---- l4 chunks: per a, zg = l2[a]*l2[b]*g3 ----
    {
        int pos = tid & 127, h = tid >> 7;
        float g3v = gts[384 + pos];
        for (int a = 0; a < 25; a++) {
            stage(stg, p4 + (155 + a*25) * 64, 1600, tid);
            float la = l2r[a * 128 + pos] * g3v;
            for (int k = 0; k < 13; k++) {
                int i = h + 2*k;
                if (i < 25) zg[i * 128 + pos] = la * l2r[i * 128 + pos];
            }
            __syncthreads();
            gpass(zg, stg, 25, pg8, cg4, acc);
            __syncthreads();
        }
    }

    // ---- write y -> ys [col][pos] (overlay on ss/l2r, both dead) + feat rows ----
    float* ys = sm + SM_SS;   // 69*128
#pragma unroll
    for (int c = 0; c < 4; c++)
#pragma unroll
        for (int pp = 0; pp < 4; pp++)
            *(u64*)(ys + (cg4 + c) * 128 + pg8 + 2*pp) = acc[c*4+pp];
    {
        int pos = tid & 127, h = tid >> 7;
        for (int k = 0; k < 3; k++) {
            int e = h + 2*k;
            if (e < 5) ys[(64 + e) * 128 + pos] = sm[SM_FEATP + e * 128 + pos];
        }
    }
    __syncthreads();

    // ---- h1 = relu([y, feat] @ w1 + b1), 3 chunks ----
#pragma unroll
    for (int pp = 0; pp < 4; pp++)
#pragma unroll
        for (int c = 0; c < 4; c++) {
            float bv = sm[SM_B1 + cg4 + c];
            acc[c*4+pp] = pk2(bv, bv);
        }
    stage(stg, w1, 1600, tid);
    __syncthreads();
    gpass(ys, stg, 25, pg8, cg4, acc);
    __syncthreads();
    stage(stg, w1 + 25*64, 1600, tid);
    __syncthreads();
    gpass(ys + 25*128, stg, 25, pg8, cg4, acc);
    __syncthreads();
    stage(stg, w1 + 50*64, 19*64, tid);
    __syncthreads();
    gpass(ys + 50*128, stg, 19, pg8, cg4, acc);
    __syncthreads();

    // ---- BN(relu(h1)) -> hb [col][pos] (overlay on ys, dead) ----
    float* hb = sm + SM_SS;
#pragma unroll
    for (int c = 0; c < 4; c++) {
        int col = cg4 + c;
        float gam = sm[SM_GAM+col], bet = sm[SM_BET+col];
        float rme = sm[SM_RME+col], rva = rsqrtf(sm[SM_RVA+col] + 1e-5f);
#pragma unroll
        for (int pp = 0; pp < 4; pp++) {
            float2 h = up2(acc[c*4+pp]);
            float bx = gam * (fmaxf(h.x, 0.f) - rme) * rva + bet;
            float by = gam * (fmaxf(h.y, 0.f) - rme) * rva + bet;
            *(u64*)(hb + col * 128 + pg8 + 2*pp) = pk2(bx, by);
        }
    }
    __syncthreads();

    // ---- h2 = relu(hb @ w2 + b2), 2 chunks of 32 rows ----
    int cg2 = cg * 2;
    u64 acc8[8];
#pragma unroll
    for (int pp = 0; pp < 4; pp++)
#pragma unroll
        for (int c = 0; c < 2; c++) {
            float bv = sm[SM_B2 + cg2 + c];
            acc8[c*4+pp] = pk2(bv, bv);
        }
    stage(stg, w2, 1024, tid);
    __syncthreads();
    gpass32(hb, stg, 32, pg8, cg2, acc8);
    __syncthreads();
    stage(stg, w2 + 1024, 1024, tid);
    __syncthreads();
    gpass32(hb + 32*128, stg, 32, pg8, cg2, acc8);
    __syncthreads();

    // ---- final: partials + reduce + tanh ----
    float* ps = sm + SM_ZG;   // 128*16
    {
        float w3a = sm[SM_W3 + cg2], w3b = sm[SM_W3 + cg2 + 1];
#pragma unroll
        for (int pp = 0; pp < 4; pp++) {
            float2 f0 = up2(acc8[0*4+pp]);
            float2 f1 = up2(acc8[1*4+pp]);
            ps[(pg8 + 2*pp)     * 16 + cg] = fmaxf(f0.x, 0.f) * w3a + fmaxf(f1.x, 0.f) * w3b;
            ps[(pg8 + 2*pp + 1) * 16 + cg] = fmaxf(f0.y, 0.f) * w3a + fmaxf(f1.y, 0.f) * w3b;
        }
    }
    __syncthreads();
    if (tid < 128) {
        float o = sm[SM_B3];
#pragma unroll
        for (int c = 0; c < 16; c += 4) {
            float4 v = *(const float4*)(ps + tid * 16 + c);
            o += v.x + v.y + v.z + v.w;
        }
        out[pos0 + tid] = 1.5f * tanhf(o);
    }
}

extern "C" void kernel_launch(void* const* d_in, const int* in_sizes, int n_in,
                              void* d_out, int out_size) {
    const float* F    = (const float*)d_in[0];
    const float* hw1  = (const float*)d_in[1];
    const float* hb1  = (const float*)d_in[2];
    const float* hw2  = (const float*)d_in[3];
    const float* hb2  = (const float*)d_in[4];
    const float* hw3  = (const float*)d_in[5];
    const float* hb3  = (const float*)d_in[6];
    const float* gw1  = (const float*)d_in[7];
    const float* gb1  = (const float*)d_in[8];
    const float* gw2  = (const float*)d_in[9];
    const float* gb2  = (const float*)d_in[10];
    const float* p1   = (const float*)d_in[11];
    const float* p1b  = (const float*)d_in[12];
    const float* p2   = (const float*)d_in[13];
    const float* p2b  = (const float*)d_in[14];
    const float* p3   = (const float*)d_in[15];
    const float* p3b  = (const float*)d_in[16];
    const float* p4   = (const float*)d_in[17];
    const float* p4b  = (const float*)d_in[18];
    const float* w1   = (const float*)d_in[19];
    const float* b1   = (const float*)d_in[20];
    const float* gm   = (const float*)d_in[21];
    const float* bt   = (const float*)d_in[22];
    const float* rmean= (const float*)d_in[23];
    const float* rvar = (const float*)d_in[24];
    const float* w2   = (const float*)d_in[25];
    const float* b2   = (const float*)d_in[26];
    const float* w3   = (const float*)d_in[27];
    const float* b3   = (const float*)d_in[28];

    cudaFuncSetAttribute(k_main, cudaFuncAttributeMaxDynamicSharedMemorySize, SMEM_BYTES);

    k_scan<<<B_, 256>>>(F);
    k_hmlp<<<(B_ * (T_ - W_) + 255) / 256, 256>>>(hw1, hb1, hw2, hb2, hw3, hb3);
    k_main<<<BT_ / PPB, NTH, SMEM_BYTES>>>(F, gw1, gb1, gw2, gb2,
                                           p1, p1b, p2, p2b, p3, p3b, p4, p4b,
                                           w1, b1, gm, bt, rmean, rvar,
                                           w2, b2, w3, b3, (float*)d_out);
}

// round 14
// speedup vs baseline: 1.0057x; 1.0041x over previous
#include <cuda_runtime.h>
#include <math.h>

#define B_  32
#define T_  2048
#define W_  10
#define BT_ (B_*T_)
#define NTH 256
#define PPB 128

typedef unsigned long long u64;

__device__ float g_ret[BT_];
__device__ float g_vol[BT_];
__device__ float g_Hl[BT_];

// ---------------- packed f32x2 helpers ----------------
__device__ __forceinline__ u64 pk2(float a, float b) {
    u64 r; asm("mov.b64 %0, {%1, %2};" : "=l"(r) : "f"(a), "f"(b)); return r;
}
__device__ __forceinline__ void fma2(u64 &d, u64 a, u64 b) {
    asm("fma.rn.f32x2 %0, %1, %2, %0;" : "+l"(d) : "l"(a), "l"(b));
}
__device__ __forceinline__ float2 up2(u64 a) {
    float2 f; asm("mov.b64 {%0, %1}, %2;" : "=f"(f.x), "=f"(f.y) : "l"(a)); return f;
}

// ---------------- K1: ret + vol ----------------
__global__ void k_scan(const float* __restrict__ F) {
    int b = blockIdx.x;
    int tid = threadIdx.x;
    __shared__ float sh[256];
    int base = tid * 8;
    const float* fb = F + (size_t)b * T_ * 5;
    float lp_prev = (base > 0) ? fb[(base - 1) * 5] : 0.f;
    float a[8];
    float run = 0.f;
#pragma unroll
    for (int k = 0; k < 8; k++) {
        int t = base + k;
        float lp = fb[t * 5];
        float r = (t == 0) ? 0.f : (lp - lp_prev);
        lp_prev = lp;
        g_ret[b * T_ + t] = r;
        run += fabsf(r);
        a[k] = run;
    }
    sh[tid] = run;
    __syncthreads();
    float acc = run;
    for (int off = 1; off < 256; off <<= 1) {
        float v = (tid >= off) ? sh[tid - off] : 0.f;
        __syncthreads();
        acc += v;
        sh[tid] = acc;
        __syncthreads();
    }
    float excl = acc - run;
#pragma unroll
    for (int k = 0; k < 8; k++) {
        int t = base + k;
        g_vol[b * T_ + t] = (excl + a[k]) / ((float)(t + 1) + 1e-8f);
    }
}

// ---------------- K2: windowed H MLP ----------------
__global__ void k_hmlp(const float* __restrict__ hw1, const float* __restrict__ hb1,
                       const float* __restrict__ hw2, const float* __restrict__ hb2,
                       const float* __restrict__ hw3, const float* __restrict__ hb3) {
    __shared__ float s1[10 * 32], sb1[32], s2[32 * 32], sb2[32], s3[32];
    __shared__ float sb3;
    int tid = threadIdx.x;
    for (int k = tid; k < 320; k += 256) s1[k] = hw1[k];
    for (int k = tid; k < 1024; k += 256) s2[k] = hw2[k];
    if (tid < 32) { sb1[tid] = hb1[tid]; sb2[tid] = hb2[tid]; s3[tid] = hw3[tid]; }
    if (tid == 0) sb3 = hb3[0];
    __syncthreads();
    const int TW = T_ - W_;
    int gid = blockIdx.x * 256 + tid;
    if (gid >= B_ * TW) return;
    int b = gid / TW, s = gid - b * TW;
    float rw[10];
#pragma unroll
    for (int j = 0; j < 10; j++) rw[j] = g_ret[b * T_ + s + j];
    float h1[32];
#pragma unroll
    for (int u = 0; u < 32; u++) {
        float acc = sb1[u];
#pragma unroll
        for (int j = 0; j < 10; j++) acc += rw[j] * s1[j * 32 + u];
        h1[u] = fmaxf(acc, 0.f);
    }
    float o = sb3;
#pragma unroll
    for (int v = 0; v < 32; v++) {
        float acc = sb2[v];
#pragma unroll
        for (int u = 0; u < 32; u++) acc += h1[u] * s2[u * 32 + v];
        o += fmaxf(acc, 0.f) * s3[v];
    }
    float Hval = 0.5f / (1.f + expf(-o));
    g_Hl[b * T_ + s + W_] = Hval;
    if (s == 0) {
        for (int t = 0; t < W_; t++) g_Hl[b * T_ + t] = Hval;
    }
}

// ---------------- SMEM layout (float offsets) ----------------
#define SM_SS    0        // 50*128 = 6400 : suffix sums S[j][e], j=0..9
#define SM_L2R   6400     // 25*128
#define SM_ZR    9600     // 25*128
#define SM_ZG    12800    // 25*128
#define SM_STG   16000    // 1600
#define SM_GTS   17600    // 4*128
#define SM_FEATP 18112    // 5*128
#define SM_PB1   18752
#define SM_PB2   18816
#define SM_PB3   18880
#define SM_PB4   18944
#define SM_B1    19008
#define SM_GAM   19072
#define SM_BET   19136
#define SM_RME   19200
#define SM_RVA   19264
#define SM_B2    19328
#define SM_W3    19360
#define SM_GW1   19392
#define SM_GB1   19456
#define SM_GW2   19488
#define SM_GB2   19616
#define SM_B3    19620
#define SM_FLOATS 19632
#define SMEM_BYTES (SM_FLOATS * 4)
// overlays: YS = 0 (69*128=8832, after l4); HB = 0 (64*128, after w1); PS = SM_ZG (2048)

__device__ __forceinline__ void stage(float* dst, const float* __restrict__ src,
                                      int nf, int tid) {
    const float4* s4 = (const float4*)src;
    float4* d4 = (float4*)dst;
    for (int k = tid; k < (nf >> 2); k += NTH) d4[k] = s4[k];
}

// GEMM pass: acc[c*4+pp] += z[row][8 pos of pg] * w[row][4 cols of cg]
__device__ __forceinline__ void gpass(const float* __restrict__ zb, const float* __restrict__ wb,
                                      int nrows, int pg8, int cg4, u64* acc) {
#pragma unroll 5
    for (int i = 0; i < nrows; i++) {
        float4 wv = *(const float4*)(wb + i * 64 + cg4);
        ulonglong2 z0 = *(const ulonglong2*)(zb + i * 128 + pg8);
        ulonglong2 z1 = *(const ulonglong2*)(zb + i * 128 + pg8 + 4);
        u64 w0 = pk2(wv.x, wv.x), w1d = pk2(wv.y, wv.y);
        u64 w2d = pk2(wv.z, wv.z), w3d = pk2(wv.w, wv.w);
        fma2(acc[0],  z0.x, w0);  fma2(acc[1],  z0.y, w0);  fma2(acc[2],  z1.x, w0);  fma2(acc[3],  z1.y, w0);
        fma2(acc[4],  z0.x, w1d); fma2(acc[5],  z0.y, w1d); fma2(acc[6],  z1.x, w1d); fma2(acc[7],  z1.y, w1d);
        fma2(acc[8],  z0.x, w2d); fma2(acc[9],  z0.y, w2d); fma2(acc[10], z1.x, w2d); fma2(acc[11], z1.y, w2d);
        fma2(acc[12], z0.x, w3d); fma2(acc[13], z0.y, w3d); fma2(acc[14], z1.x, w3d); fma2(acc[15], z1.y, w3d);
    }
}

// 32-col GEMM pass: acc[c*4+pp], c=0..1
__device__ __forceinline__ void gpass32(const float* __restrict__ zb, const float* __restrict__ wb,
                                        int nrows, int pg8, int cg2, u64* acc) {
#pragma unroll 8
    for (int i = 0; i < nrows; i++) {
        float2 wv = *(const float2*)(wb + i * 32 + cg2);
        ulonglong2 z0 = *(const ulonglong2*)(zb + i * 128 + pg8);
        ulonglong2 z1 = *(const ulonglong2*)(zb + i * 128 + pg8 + 4);
        u64 w0 = pk2(wv.x, wv.x), w1d = pk2(wv.y, wv.y);
        fma2(acc[0], z0.x, w0);  fma2(acc[1], z0.y, w0);  fma2(acc[2], z1.x, w0);  fma2(acc[3], z1.y, w0);
        fma2(acc[4], z0.x, w1d); fma2(acc[5], z0.y, w1d); fma2(acc[6], z1.x, w1d); fma2(acc[7], z1.y, w1d);
    }
}

// ---------------- K3: main fused kernel ----------------
__global__ void __launch_bounds__(NTH) k_main(
    const float* __restrict__ F,
    const float* __restrict__ gw1, const float* __restrict__ gb1,
    const float* __restrict__ gw2, const float* __restrict__ gb2,
    const float* __restrict__ p1,  const float* __restrict__ p1b,
    const float* __restrict__ p2,  const float* __restrict__ p2b,
    const float* __restrict__ p3,  const float* __restrict__ p3b,
    const float* __restrict__ p4,  const float* __restrict__ p4b,
    const float* __restrict__ w1,  const float* __restrict__ b1,
    const float* __restrict__ gamma, const float* __restrict__ beta,
    const float* __restrict__ rmean, const float* __restrict__ rvar,
    const float* __restrict__ w2,  const float* __restrict__ b2,
    const float* __restrict__ w3,  const float* __restrict__ b3,
    float* __restrict__ out)
{
    extern __shared__ float sm[];
    int tid = threadIdx.x;
    int pg = tid >> 4, cg = tid & 15;
    int pg8 = pg * 8, cg4 = cg * 4;
    int pos0 = blockIdx.x * PPB;
    float* ss  = sm + SM_SS;
    float* l2r = sm + SM_L2R;
    float* zr  = sm + SM_ZR;
    float* zg  = sm + SM_ZG;
    float* stg = sm + SM_STG;
    float* gts = sm + SM_GTS;

    // ---- phase 0: params (tid>=128) + signature suffix sums (tid<128) ----
    if (tid >= 128 && tid < 192) {
        int k = tid - 128;
        sm[SM_PB1 + k] = p1b[k]; sm[SM_PB2 + k] = p2b[k];
        sm[SM_PB3 + k] = p3b[k]; sm[SM_PB4 + k] = p4b[k];
        sm[SM_B1 + k] = b1[k];  sm[SM_GAM + k] = gamma[k];
        sm[SM_BET + k] = beta[k]; sm[SM_RME + k] = rmean[k];
        sm[SM_RVA + k] = rvar[k]; sm[SM_GW1 + k] = gw1[k];
    } else if (tid >= 192 && tid < 224) {
        int k = tid - 192;
        sm[SM_B2 + k] = b2[k]; sm[SM_W3 + k] = w3[k]; sm[SM_GB1 + k] = gb1[k];
    } else if (tid >= 224) {
        int k = tid - 224;
        for (int k2 = k; k2 < 128; k2 += 32) sm[SM_GW2 + k2] = gw2[k2];
        if (k < 4)  sm[SM_GB2 + k] = gb2[k];
        if (k == 4) sm[SM_B3] = b3[0];
    }

    int mypos = pos0 + (tid & 127);
    int myt = mypos & (T_ - 1);
    int myb = mypos >> 11;
    const float* fb = F + (size_t)myb * T_ * 5;

    if (tid < 128) {
        float S[5] = {0.f,0.f,0.f,0.f,0.f};
        float l2f[25];
#pragma unroll
        for (int i = 0; i < 25; i++) l2f[i] = 0.f;
        float rowH[5];
#pragma unroll
        for (int e = 0; e < 5; e++) {
            rowH[e] = fb[myt * 5 + e];
            sm[SM_FEATP + e * 128 + tid] = rowH[e];
        }
#pragma unroll
        for (int r = W_ - 1; r >= 0; r--) {
            int i0 = myt - W_ + r;
            bool valid = (i0 >= 0);
            float Dw[5], rowL[5];
#pragma unroll
            for (int e = 0; e < 5; e++) {
                rowL[e] = valid ? fb[i0 * 5 + e] : 0.f;
                Dw[e] = valid ? (rowH[e] - rowL[e]) : 0.f;
            }
#pragma unroll
            for (int e = 0; e < 5; e++) {
                S[e] += Dw[e];
                ss[(r * 5 + e) * 128 + tid] = S[e];
            }
#pragma unroll
            for (int e = 0; e < 5; e++)
#pragma unroll
                for (int f = 0; f < 5; f++) l2f[e * 5 + f] += Dw[e] * S[f];
#pragma unroll
            for (int e = 0; e < 5; e++) rowH[e] = rowL[e];
        }
#pragma unroll
        for (int i = 0; i < 25; i++) l2r[i * 128 + tid] = l2f[i];
    }
    __syncthreads();

    // ---- phase 1: gate (tid<128) + stage lvl1 weights ----
    stage(stg +   0, p1, 320, tid);
    stage(stg + 320, p2, 320, tid);
    stage(stg + 640, p3, 320, tid);
    stage(stg + 960, p4, 320, tid);
    if (tid < 128) {
        float Hv = g_Hl[mypos], vv = g_vol[mypos];
        float L0 = sm[SM_GB2+0], L1 = sm[SM_GB2+1], L2 = sm[SM_GB2+2], L3 = sm[SM_GB2+3];
#pragma unroll
        for (int u = 0; u < 32; u++) {
            float gh = fmaxf(Hv * sm[SM_GW1 + u] + vv * sm[SM_GW1 + 32 + u] + sm[SM_GB1 + u], 0.f);
            L0 += gh * sm[SM_GW2 + u*4 + 0];
            L1 += gh * sm[SM_GW2 + u*4 + 1];
            L2 += gh * sm[SM_GW2 + u*4 + 2];
            L3 += gh * sm[SM_GW2 + u*4 + 3];
        }
        float mx = fmaxf(fmaxf(L0,L1), fmaxf(L2,L3));
        float e0 = expf(L0-mx), e1 = expf(L1-mx), e2 = expf(L2-mx), e3 = expf(L3-mx);
        float inv = 1.f / (e0+e1+e2+e3);
        gts[       tid] = e0 * inv;
        gts[128 + tid] = (myt >= 1) ? e1 * inv : 0.f;
        gts[256 + tid] = (myt >= 2) ? e2 * inv : 0.f;
        gts[384 + tid] = (myt >= 3) ? e3 * inv : 0.f;
    }
    __syncthreads();

    // ---- acc init from gated biases + lvl1 zg gen ----
    u64 acc[16];
#pragma unroll
    for (int pp = 0; pp < 4; pp++) {
        int pl0 = pg8 + 2*pp;
        float ga0 = gts[pl0],     ga1 = gts[128+pl0], ga2 = gts[256+pl0], ga3 = gts[384+pl0];
        float gb0 = gts[pl0+1],   gb1v = gts[128+pl0+1], gb2v = gts[256+pl0+1], gb3v = gts[384+pl0+1];
#pragma unroll
        for (int c = 0; c < 4; c++) {
            int col = cg4 + c;
            float ve = ga0*sm[SM_PB1+col] + ga1*sm[SM_PB2+col] + ga2*sm[SM_PB3+col] + ga3*sm[SM_PB4+col];
            float vo = gb0*sm[SM_PB1+col] + gb1v*sm[SM_PB2+col] + gb2v*sm[SM_PB3+col] + gb3v*sm[SM_PB4+col];
            acc[c*4+pp] = pk2(ve, vo);
        }
    }
    {
        int pos = tid & 127, h = tid >> 7;
        for (int k = 0; k < 10; k++) {
            int i = h + 2*k;
            if (i < 20) {
                int lvl = i / 5, e = i - 5*lvl;
                zg[i * 128 + pos] = ss[e * 128 + pos] * gts[lvl * 128 + pos];
            }
        }
    }
    __syncthreads();
    gpass(zg, stg, 20, pg8, cg4, acc);
    __syncthreads();

    // ---- l2 chunks: p2(g1), p3(g2), p4(g3) ----
    {
        int pos = tid & 127, h = tid >> 7;
        const float* pmat[3] = { p2, p3, p4 };
        for (int m = 0; m < 3; m++) {
            stage(stg, pmat[m] + 5 * 64, 1600, tid);
            float gv = gts[(m+1) * 128 + pos];
            for (int k = 0; k < 13; k++) {
                int i = h + 2*k;
                if (i < 25) zg[i * 128 + pos] = l2r[i * 128 + pos] * gv;
            }
            __syncthreads();
            gpass(zg, stg, 25, pg8, cg4, acc);
            __syncthreads();
        }
    }

    // ---- l3 chunks: per dd, gen zr once, gate for p3(g2) then p4(g3) ----
    {
        int pos = tid & 127, h = tid >> 7;
        for (int dd = 0; dd < 5; dd++) {
            // cooperative raw l3 chunk gen from suffix sums
            float Tot = ss[dd * 128 + pos];
            float ssj[5] = {0.f,0.f,0.f,0.f,0.f};
            if (h == 0) {
                float a0[5], a1[5], a2[5];
#pragma unroll
                for (int f = 0; f < 5; f++) { a0[f]=0.f; a1[f]=0.f; a2[f]=0.f; }
#pragma unroll
                for (int j = 9; j >= 0; j--) {
                    float ssc[5];
#pragma unroll
                    for (int e = 0; e < 5; e++) ssc[e] = ss[(j*5+e)*128 + pos];
                    float pj = Tot - ssc[dd];
                    float t0 = pj * (ssc[0]-ssj[0]);
                    float t1 = pj * (ssc[1]-ssj[1]);
                    float t2 = pj * (ssc[2]-ssj[2]);
#pragma unroll
                    for (int f = 0; f < 5; f++) {
                        a0[f] += t0 * ssc[f];
                        a1[f] += t1 * ssc[f];
                        a2[f] += t2 * ssc[f];
                    }
#pragma unroll
                    for (int e = 0; e < 5; e++) ssj[e] = ssc[e];
                }
#pragma unroll
                for (int f = 0; f < 5; f++) {
                    zr[(0*5+f)*128+pos] = a0[f];
                    zr[(1*5+f)*128+pos] = a1[f];
                    zr[(2*5+f)*128+pos] = a2[f];
                }
            } else {
                float a3[5], a4[5];
#pragma unroll
                for (int f = 0; f < 5; f++) { a3[f]=0.f; a4[f]=0.f; }
#pragma unroll
                for (int j = 9; j >= 0; j--) {
                    float ssc[5];
#pragma unroll
                    for (int e = 0; e < 5; e++) ssc[e] = ss[(j*5+e)*128 + pos];
                    float pj = Tot - ssc[dd];
                    float t3 = pj * (ssc[3]-ssj[3]);
                    float t4 = pj * (ssc[4]-ssj[4]);
#pragma unroll
                    for (int f = 0; f < 5; f++) {
                        a3[f] += t3 * ssc[f];
                        a4[f] += t4 * ssc[f];
                    }
#pragma unroll
                    for (int e = 0; e < 5; e++) ssj[e] = ssc[e];
                }
#pragma unroll
                for (int f = 0; f < 5; f++) {
                    zr[(3*5+f)*128+pos] = a3[f];
                    zr[(4*5+f)*128+pos] = a4[f];
                }
            }
            __syncthreads();
            // two gated passes
            for (int m = 0; m < 2; m++) {
                const float* wsrc = (m == 0) ? (p3 + (30 + dd*25) * 64) : (p4 + (30 + dd*25) * 64);
                stage(stg, wsrc, 1600, tid);
                float gv = gts[(m+2) * 128 + pos];
                for (int k = 0; k < 13; k++) {
                    int i = h + 2*k;
                    if (i < 25) zg[i * 128 + pos] = zr[i * 128 + pos] * gv;
                }
                __syncthreads();
                gpass(zg, stg, 25, pg8, cg4, acc);
                __syncthreads();
            }
        }
    }

    // ---- l4 chunks: per a, zg = l2[a]*l2[b]*g3 ----
    {
        int pos = tid & 127, h = tid >> 7;
        float g3v = gts[384 + pos];
        for (int a = 0; a < 25; a++) {
            stage(stg, p4 + (155 + a*25) * 64, 1600, tid);
            float la = l2r[a * 128 + pos] * g3v;
            for (int k = 0; k < 13; k++) {
                int i = h + 2*k;
                if (i < 25) zg[i * 128 + pos] = la * l2r[i * 128 + pos];
            }
            __syncthreads();
            gpass(zg, stg, 25, pg8, cg4, acc);
            __syncthreads();
        }
    }

    // ---- write y -> ys [col][pos] (overlay on ss/l2r, both dead) + feat rows ----
    float* ys = sm + SM_SS;   // 69*128
#pragma unroll
    for (int c = 0; c < 4; c++)
#pragma unroll
        for (int pp = 0; pp < 4; pp++)
            *(u64*)(ys + (cg4 + c) * 128 + pg8 + 2*pp) = acc[c*4+pp];
    {
        int pos = tid & 127, h = tid >> 7;
        for (int k = 0; k < 3; k++) {
            int e = h + 2*k;
            if (e < 5) ys[(64 + e) * 128 + pos] = sm[SM_FEATP + e * 128 + pos];
        }
    }
    __syncthreads();

    // ---- h1 = relu([y, feat] @ w1 + b1), 3 chunks ----
#pragma unroll
    for (int pp = 0; pp < 4; pp++)
#pragma unroll
        for (int c = 0; c < 4; c++) {
            float bv = sm[SM_B1 + cg4 + c];
            acc[c*4+pp] = pk2(bv, bv);
        }
    stage(stg, w1, 1600, tid);
    __syncthreads();
    gpass(ys, stg, 25, pg8, cg4, acc);
    __syncthreads();
    stage(stg, w1 + 25*64, 1600, tid);
    __syncthreads();
    gpass(ys + 25*128, stg, 25, pg8, cg4, acc);
    __syncthreads();
    stage(stg, w1 + 50*64, 19*64, tid);
    __syncthreads();
    gpass(ys + 50*128, stg, 19, pg8, cg4, acc);
    __syncthreads();

    // ---- BN(relu(h1)) -> hb [col][pos] (overlay on ys, dead) ----
    float* hb = sm + SM_SS;
#pragma unroll
    for (int c = 0; c < 4; c++) {
        int col = cg4 + c;
        float gam = sm[SM_GAM+col], bet = sm[SM_BET+col];
        float rme = sm[SM_RME+col], rva = rsqrtf(sm[SM_RVA+col] + 1e-5f);
#pragma unroll
        for (int pp = 0; pp < 4; pp++) {
            float2 h = up2(acc[c*4+pp]);
            float bx = gam * (fmaxf(h.x, 0.f) - rme) * rva + bet;
            float by = gam * (fmaxf(h.y, 0.f) - rme) * rva + bet;
            *(u64*)(hb + col * 128 + pg8 + 2*pp) = pk2(bx, by);
        }
    }
    __syncthreads();

    // ---- h2 = relu(hb @ w2 + b2), 2 chunks of 32 rows ----
    int cg2 = cg * 2;
    u64 acc8[8];
#pragma unroll
    for (int pp = 0; pp < 4; pp++)
#pragma unroll
        for (int c = 0; c < 2; c++) {
            float bv = sm[SM_B2 + cg2 + c];
            acc8[c*4+pp] = pk2(bv, bv);
        }
    stage(stg, w2, 1024, tid);
    __syncthreads();
    gpass32(hb, stg, 32, pg8, cg2, acc8);
    __syncthreads();
    stage(stg, w2 + 1024, 1024, tid);
    __syncthreads();
    gpass32(hb + 32*128, stg, 32, pg8, cg2, acc8);
    __syncthreads();

    // ---- final: partials + reduce + tanh ----
    float* ps = sm + SM_ZG;   // 128*16
    {
        float w3a = sm[SM_W3 + cg2], w3b = sm[SM_W3 + cg2 + 1];
#pragma unroll
        for (int pp = 0; pp < 4; pp++) {
            float2 f0 = up2(acc8[0*4+pp]);
            float2 f1 = up2(acc8[1*4+pp]);
            ps[(pg8 + 2*pp)     * 16 + cg] = fmaxf(f0.x, 0.f) * w3a + fmaxf(f1.x, 0.f) * w3b;
            ps[(pg8 + 2*pp + 1) * 16 + cg] = fmaxf(f0.y, 0.f) * w3a + fmaxf(f1.y, 0.f) * w3b;
        }
    }
    __syncthreads();
    if (tid < 128) {
        float o = sm[SM_B3];
#pragma unroll
        for (int c = 0; c < 16; c += 4) {
            float4 v = *(const float4*)(ps + tid * 16 + c);
            o += v.x + v.y + v.z + v.w;
        }
        out[pos0 + tid] = 1.5f * tanhf(o);
    }
}

extern "C" void kernel_launch(void* const* d_in, const int* in_sizes, int n_in,
                              void* d_out, int out_size) {
    const float* F    = (const float*)d_in[0];
    const float* hw1  = (const float*)d_in[1];
    const float* hb1  = (const float*)d_in[2];
    const float* hw2  = (const float*)d_in[3];
    const float* hb2  = (const float*)d_in[4];
    const float* hw3  = (const float*)d_in[5];
    const float* hb3  = (const float*)d_in[6];
    const float* gw1  = (const float*)d_in[7];
    const float* gb1  = (const float*)d_in[8];
    const float* gw2  = (const float*)d_in[9];
    const float* gb2  = (const float*)d_in[10];
    const float* p1   = (const float*)d_in[11];
    const float* p1b  = (const float*)d_in[12];
    const float* p2   = (const float*)d_in[13];
    const float* p2b  = (const float*)d_in[14];
    const float* p3   = (const float*)d_in[15];
    const float* p3b  = (const float*)d_in[16];
    const float* p4   = (const float*)d_in[17];
    const float* p4b  = (const float*)d_in[18];
    const float* w1   = (const float*)d_in[19];
    const float* b1   = (const float*)d_in[20];
    const float* gm   = (const float*)d_in[21];
    const float* bt   = (const float*)d_in[22];
    const float* rmean= (const float*)d_in[23];
    const float* rvar = (const float*)d_in[24];
    const float* w2   = (const float*)d_in[25];
    const float* b2   = (const float*)d_in[26];
    const float* w3   = (const float*)d_in[27];
    const float* b3   = (const float*)d_in[28];

    cudaFuncSetAttribute(k_main, cudaFuncAttributeMaxDynamicSharedMemorySize, SMEM_BYTES);

    k_scan<<<B_, 256>>>(F);
    k_hmlp<<<(B_ * (T_ - W_) + 255) / 256, 256>>>(hw1, hb1, hw2, hb2, hw3, hb3);
    k_main<<<BT_ / PPB, NTH, SMEM_BYTES>>>(F, gw1, gb1, gw2, gb2,
                                           p1, p1b, p2, p2b, p3, p3b, p4, p4b,
                                           w1, b1, gm, bt, rmean, rvar,
                                           w2, b2, w3, b3, (float*)d_out);
}